// round 4
// baseline (speedup 1.0000x reference)
#include <cuda_runtime.h>
#include <math.h>

#define NB 2048
#define BN_EPS 1e-5

// ---- stats buffer layout (doubles) ----
#define ST1_SUM 0     // 16
#define ST1_SQ  16    // 16
#define ST2_SUM 32    // 2
#define ST2_SQ  34    // 2
#define STH1_SUM 36   // 2
#define STH1_SQ  38   // 2
#define STH2_SUM 40   // 2
#define STH2_SQ  42   // 2
#define ST3_SUM 44    // 32
#define ST3_SQ  76    // 32
#define ST_LOSS 108
#define ST_TOTAL 109

__device__ double g_stats[ST_TOTAL];
__device__ float g_y1[NB * 16 * 196];   // conv1 raw out (B,16,14,14)
__device__ float g_y2[NB * 98];         // conv2 raw out (B,2,7,7)
__device__ float g_h1[NB * 98];         // dec conv1 raw out
__device__ float g_h2[NB * 98];         // dec conv2 raw out
__device__ float g_y3[NB * 32 * 196];   // convT1 raw out (B,32,14,14)

// ---- double-float compensated accumulate: s+c += a*b (exact product via fma) ----
__device__ __forceinline__ void df_acc(float& s, float& c, float a, float b) {
    float p = __fmul_rn(a, b);
    float e = __fmaf_rn(a, b, -p);         // exact product low part
    float t = __fadd_rn(s, p);             // TwoSum(s, p)
    float bv = __fsub_rn(t, s);
    float err = __fadd_rn(__fsub_rn(s, __fsub_rn(t, bv)), __fsub_rn(p, bv));
    s = t;
    c = __fadd_rn(c, __fadd_rn(err, e));
}
__device__ __forceinline__ float df_round(float s, float c) { return __fadd_rn(s, c); }

// fused BN coefficients (decoder path; gammas=1/betas=0 so rounding slack is fine)
__device__ __forceinline__ void bn_coef(double sum, double sq, double N,
                                        float g, float b, float* sc, float* sh) {
    double mu = sum / N;
    double var = sq / N - mu * mu;
    double s = (double)g / sqrt(var + BN_EPS);
    *sc = (float)s;
    *sh = (float)((double)b - mu * s);
}

// encoder BN: fp32 mu / var rounded once from exact fp64 stats; r via libdevice rsqrtf
__device__ __forceinline__ void bn_mur(double sum, double sq, double N,
                                       float* muf, float* rf) {
    double mu = sum / N;
    double var = sq / N - mu * mu;
    float vf = (float)var;
    *muf = (float)mu;
    *rf = rsqrtf(__fadd_rn(vf, 1e-5f));    // == __nv_rsqrtf, XLA's lax.rsqrt lowering
}

// exact reference BN+ReLU: relu(((x - mu) * r) * g + b), g/b via fma (exact for 1/0)
__device__ __forceinline__ float bn_ref(float x, float mu, float r, float g, float b) {
    float t = __fmul_rn(__fsub_rn(x, mu), r);
    return fmaxf(__fmaf_rn(t, g, b), 0.f);
}

// ---------------- K0: zero stats ----------------
__global__ void k0_zero() {
    int t = threadIdx.x;
    if (t < ST_TOTAL) g_stats[t] = 0.0;
}

// ---------------- K1: conv1 (1->16, 4x4, s2, p1) + fp64 stats ----------------
__global__ void __launch_bounds__(224) k1_conv1(const float* __restrict__ x,
                                                const float* __restrict__ w,
                                                const float* __restrict__ bias) {
    __shared__ float sx[784];
    __shared__ float sw[256];
    __shared__ float sb[16];
    __shared__ double sA[16], sQ[16];
    int b = blockIdx.x, t = threadIdx.x;

    for (int i = t; i < 784; i += 224) sx[i] = x[b * 784 + i];
    for (int i = t; i < 256; i += 224) sw[i] = w[i];
    if (t < 16) { sb[t] = bias[t]; sA[t] = 0.0; sQ[t] = 0.0; }
    __syncthreads();

    bool act = t < 196;
    int oy = act ? t / 14 : 0, ox = act ? t % 14 : 0;
    float win[16];
#pragma unroll
    for (int k = 0; k < 16; k++) win[k] = 0.f;
    if (act) {
#pragma unroll
        for (int ky = 0; ky < 4; ky++) {
            int iy = 2 * oy - 1 + ky;
#pragma unroll
            for (int kx = 0; kx < 4; kx++) {
                int ix = 2 * ox - 1 + kx;
                win[ky * 4 + kx] = (iy >= 0 && iy < 28 && ix >= 0 && ix < 28) ? sx[iy * 28 + ix] : 0.f;
            }
        }
    }
#pragma unroll
    for (int c = 0; c < 16; c++) {
        float v = 0.f;
        if (act) {
            float s = 0.f, comp = 0.f;
#pragma unroll
            for (int k = 0; k < 16; k++) df_acc(s, comp, win[k], sw[c * 16 + k]);
            // conv result correctly rounded, then bias added after (ref order)
            v = __fadd_rn(df_round(s, comp), sb[c]);
            g_y1[(b * 16 + c) * 196 + t] = v;
        }
        double ds = (double)v, ds2 = (double)v * (double)v;
#pragma unroll
        for (int o = 16; o; o >>= 1) {
            ds  += __shfl_down_sync(0xffffffffu, ds, o);
            ds2 += __shfl_down_sync(0xffffffffu, ds2, o);
        }
        if ((t & 31) == 0) { atomicAdd(&sA[c], ds); atomicAdd(&sQ[c], ds2); }
    }
    __syncthreads();
    if (t < 16) {
        atomicAdd(&g_stats[ST1_SUM + t], sA[t]);
        atomicAdd(&g_stats[ST1_SQ + t], sQ[t]);
    }
}

// ---------------- K2: BN1+ReLU -> conv2 (16->2, 4x4, s2, p1) + fp64 stats ----------------
__global__ void __launch_bounds__(128) k2_conv2(const float* __restrict__ w2,
                                                const float* __restrict__ bias2,
                                                const float* __restrict__ g1,
                                                const float* __restrict__ b1) {
    __shared__ float s1[3136];
    __shared__ float sw[512];
    __shared__ float smu[16], sr[16], sg[16], sbb[16];
    __shared__ double sA[2], sQ[2];
    int b = blockIdx.x, t = threadIdx.x;

    if (t < 16) {
        bn_mur(g_stats[ST1_SUM + t], g_stats[ST1_SQ + t], 401408.0, &smu[t], &sr[t]);
        sg[t] = g1[t]; sbb[t] = b1[t];
    }
    if (t < 2) { sA[t] = 0.0; sQ[t] = 0.0; }
    for (int i = t; i < 512; i += 128) sw[i] = w2[i];
    __syncthreads();

    for (int i = t; i < 3136; i += 128) {
        int c = i / 196;
        s1[i] = bn_ref(g_y1[b * 3136 + i], smu[c], sr[c], sg[c], sbb[c]);
    }
    __syncthreads();

    if (t < 98) {
        int c = t / 49, p = t % 49, oy = p / 7, ox = p % 7;
        float s = 0.f, comp = 0.f;   // compensated 256-term reduction
#pragma unroll
        for (int ic = 0; ic < 16; ic++) {
#pragma unroll
            for (int ky = 0; ky < 4; ky++) {
                int iy = 2 * oy - 1 + ky;
                if (iy < 0 || iy >= 14) continue;
#pragma unroll
                for (int kx = 0; kx < 4; kx++) {
                    int ix = 2 * ox - 1 + kx;
                    if (ix < 0 || ix >= 14) continue;
                    df_acc(s, comp, s1[ic * 196 + iy * 14 + ix],
                           sw[c * 256 + ic * 16 + ky * 4 + kx]);
                }
            }
        }
        float v = __fadd_rn(df_round(s, comp), bias2[c]);
        g_y2[b * 98 + t] = v;
        atomicAdd(&sA[c], (double)v); atomicAdd(&sQ[c], (double)v * (double)v);
    }
    __syncthreads();
    if (t < 2) {
        atomicAdd(&g_stats[ST2_SUM + t], sA[t]);
        atomicAdd(&g_stats[ST2_SQ + t], sQ[t]);
    }
}

// ------- K3: BN2+ReLU -> VQ (ref-exact fp32 d2) -> dec conv1 (1x1) + stats -------
__global__ void __launch_bounds__(128) k3_vq(const float* __restrict__ embed,
                                             const float* __restrict__ g2,
                                             const float* __restrict__ b2,
                                             const float* __restrict__ dw1,
                                             const float* __restrict__ dbi1,
                                             float* __restrict__ cls) {
    __shared__ float se[1024];
    __shared__ float sn[512];
    __shared__ float sq[98], qt[98];
    __shared__ float smu[2], sr[2], sg[2], sbb[2];
    __shared__ float bd[98];
    __shared__ int bidx[98];
    __shared__ double sA[2], sQ[2], sloss;
    int b = blockIdx.x, t = threadIdx.x;

    if (t < 2) {
        bn_mur(g_stats[ST2_SUM + t], g_stats[ST2_SQ + t], 100352.0, &smu[t], &sr[t]);
        sg[t] = g2[t]; sbb[t] = b2[t];
        sA[t] = 0.0; sQ[t] = 0.0;
    }
    if (t == 2) sloss = 0.0;
    for (int i = t; i < 1024; i += 128) se[i] = embed[i];
    __syncthreads();
    // ee_k = e0*e0 + e1*e1, exact ref order
    for (int i = t; i < 512; i += 128)
        sn[i] = __fadd_rn(__fmul_rn(se[2 * i], se[2 * i]),
                          __fmul_rn(se[2 * i + 1], se[2 * i + 1]));
    for (int i = t; i < 98; i += 128) {
        int c = i / 49;
        sq[i] = bn_ref(g_y2[b * 98 + i], smu[c], sr[c], sg[c], sbb[c]);
    }
    __syncthreads();

    if (t < 98) {
        int n = t >> 1;
        float q0 = sq[2 * n], q1 = sq[2 * n + 1];
        float qq = __fadd_rn(__fmul_rn(q0, q0), __fmul_rn(q1, q1));
        int k0 = (t & 1) * 256;
        float best = 3.4e38f; int bi = k0;
        for (int k = k0; k < k0 + 256; k++) {
            // ref d2: (qq + ee) - 2*dot, dot = fma(q1,e1, q0*e0) (ascending-k chain)
            float dot = __fmaf_rn(q1, se[2 * k + 1], __fmul_rn(q0, se[2 * k]));
            float d = __fsub_rn(__fadd_rn(qq, sn[k]), __fmul_rn(2.f, dot));
            if (d < best) { best = d; bi = k; }
        }
        bd[t] = best; bidx[t] = bi;
    }
    __syncthreads();

    if (t < 49) {
        int k = (bd[2 * t + 1] < bd[2 * t]) ? bidx[2 * t + 1] : bidx[2 * t];
        float ea = se[2 * k], eb = se[2 * k + 1];
        qt[2 * t] = ea; qt[2 * t + 1] = eb;
        if (cls) cls[b * 49 + t] = (float)k;
        float da = ea - sq[2 * t], db = eb - sq[2 * t + 1];
        atomicAdd(&sloss, (double)da * da + (double)db * db);
    }
    __syncthreads();

    if (t < 98) {
        int o = t / 49, p = t % 49;
        float v = fmaf(dw1[o * 2], qt[p], fmaf(dw1[o * 2 + 1], qt[49 + p], dbi1[o]));
        g_h1[b * 98 + t] = v;
        atomicAdd(&sA[o], (double)v); atomicAdd(&sQ[o], (double)v * (double)v);
    }
    __syncthreads();
    if (t < 2) {
        atomicAdd(&g_stats[STH1_SUM + t], sA[t]);
        atomicAdd(&g_stats[STH1_SQ + t], sQ[t]);
    }
    if (t == 2) atomicAdd(&g_stats[ST_LOSS], sloss);
}

// ---------------- K4: BN(h1)+ReLU -> dec conv2 (1x1) + stats ----------------
__global__ void __launch_bounds__(128) k4_dec2(const float* __restrict__ dg1,
                                               const float* __restrict__ dbb1,
                                               const float* __restrict__ dw2,
                                               const float* __restrict__ dbi2) {
    __shared__ float hb[98];
    __shared__ float sc[2], sh[2];
    __shared__ double sA[2], sQ[2];
    int b = blockIdx.x, t = threadIdx.x;
    if (t < 2) {
        bn_coef(g_stats[STH1_SUM + t], g_stats[STH1_SQ + t], 100352.0,
                dg1[t], dbb1[t], &sc[t], &sh[t]);
        sA[t] = 0.0; sQ[t] = 0.0;
    }
    __syncthreads();
    if (t < 98) {
        int c = t / 49;
        hb[t] = fmaxf(fmaf(g_h1[b * 98 + t], sc[c], sh[c]), 0.f);
    }
    __syncthreads();
    if (t < 98) {
        int o = t / 49, p = t % 49;
        float v = fmaf(dw2[o * 2], hb[p], fmaf(dw2[o * 2 + 1], hb[49 + p], dbi2[o]));
        g_h2[b * 98 + t] = v;
        atomicAdd(&sA[o], (double)v); atomicAdd(&sQ[o], (double)v * (double)v);
    }
    __syncthreads();
    if (t < 2) {
        atomicAdd(&g_stats[STH2_SUM + t], sA[t]);
        atomicAdd(&g_stats[STH2_SQ + t], sQ[t]);
    }
}

// ---------------- K5: BN(h2)+ReLU -> convT1 (2->32, 4x4, s2, p1) + stats ----------------
__global__ void __launch_bounds__(224) k5_convt1(const float* __restrict__ dg2,
                                                 const float* __restrict__ dbb2,
                                                 const float* __restrict__ tw1,
                                                 const float* __restrict__ tbi1) {
    __shared__ float si[98];
    __shared__ float sw[1024];
    __shared__ float sc[2], sh[2];
    __shared__ double sA[32], sQ[32];
    __shared__ float sb[32];
    int b = blockIdx.x, t = threadIdx.x;

    if (t < 2) {
        bn_coef(g_stats[STH2_SUM + t], g_stats[STH2_SQ + t], 100352.0,
                dg2[t], dbb2[t], &sc[t], &sh[t]);
    }
    if (t < 32) { sA[t] = 0.0; sQ[t] = 0.0; sb[t] = tbi1[t]; }
    for (int i = t; i < 1024; i += 224) sw[i] = tw1[i];
    __syncthreads();
    for (int i = t; i < 98; i += 224) {
        int c = i / 49;
        si[i] = fmaxf(fmaf(g_h2[b * 98 + i], sc[c], sh[c]), 0.f);
    }
    __syncthreads();

    bool act = t < 196;
    int y = act ? t / 14 : 0, x = act ? t % 14 : 0;
    int pary = (y + 1) & 1, parx = (x + 1) & 1;
    int iya = (y + 1 - pary) >> 1, iyb = iya - 1;
    int ixa = (x + 1 - parx) >> 1, ixb = ixa - 1;
    bool vya = act && (iya < 7), vyb = act && (iyb >= 0);
    bool vxa = (ixa < 7), vxb = (ixb >= 0);
    int kya = pary, kyb = pary + 2, kxa = parx, kxb = parx + 2;
    int off_aa = iya * 7 + ixa, kk_aa = kya * 4 + kxa;
    int off_ab = iya * 7 + ixb, kk_ab = kya * 4 + kxb;
    int off_ba = iyb * 7 + ixa, kk_ba = kyb * 4 + kxa;
    int off_bb = iyb * 7 + ixb, kk_bb = kyb * 4 + kxb;
    bool c_aa = vya && vxa, c_ab = vya && vxb, c_ba = vyb && vxa, c_bb = vyb && vxb;

#pragma unroll 4
    for (int o = 0; o < 32; o++) {
        float v = 0.f;
        if (act) {
            v = sb[o];
            if (c_aa) { v = fmaf(si[off_aa], sw[o * 16 + kk_aa], v); v = fmaf(si[49 + off_aa], sw[512 + o * 16 + kk_aa], v); }
            if (c_ab) { v = fmaf(si[off_ab], sw[o * 16 + kk_ab], v); v = fmaf(si[49 + off_ab], sw[512 + o * 16 + kk_ab], v); }
            if (c_ba) { v = fmaf(si[off_ba], sw[o * 16 + kk_ba], v); v = fmaf(si[49 + off_ba], sw[512 + o * 16 + kk_ba], v); }
            if (c_bb) { v = fmaf(si[off_bb], sw[o * 16 + kk_bb], v); v = fmaf(si[49 + off_bb], sw[512 + o * 16 + kk_bb], v); }
            g_y3[(b * 32 + o) * 196 + t] = v;
        }
        float s = v, s2 = v * v;
#pragma unroll
        for (int off = 16; off; off >>= 1) {
            s  += __shfl_down_sync(0xffffffffu, s, off);
            s2 += __shfl_down_sync(0xffffffffu, s2, off);
        }
        if ((t & 31) == 0) { atomicAdd(&sA[o], (double)s); atomicAdd(&sQ[o], (double)s2); }
    }
    __syncthreads();
    if (t < 32) {
        atomicAdd(&g_stats[ST3_SUM + t], sA[t]);
        atomicAdd(&g_stats[ST3_SQ + t], sQ[t]);
    }
}

// ---------------- K6: BN(y3)+ReLU -> convT2 (32->1, 4x4, s2, p1) -> sigmoid ----------------
__global__ void __launch_bounds__(256) k6_convt2(const float* __restrict__ dg3,
                                                 const float* __restrict__ dbb3,
                                                 const float* __restrict__ tw2,
                                                 const float* __restrict__ tbi2,
                                                 float* __restrict__ outp,
                                                 float* __restrict__ lossp) {
    __shared__ float si[6272];
    __shared__ float sw[512];
    __shared__ float sc[32], sh[32];
    int b = blockIdx.x, t = threadIdx.x;

    if (t < 32) {
        bn_coef(g_stats[ST3_SUM + t], g_stats[ST3_SQ + t], 401408.0,
                dg3[t], dbb3[t], &sc[t], &sh[t]);
    }
    for (int i = t; i < 512; i += 256) sw[i] = tw2[i];
    __syncthreads();
    for (int i = t; i < 6272; i += 256) {
        int c = i / 196;
        si[i] = fmaxf(fmaf(g_y3[b * 6272 + i], sc[c], sh[c]), 0.f);
    }
    __syncthreads();

    float bias = tbi2[0];
    for (int idx = t; idx < 784; idx += 256) {
        int y = idx / 28, x = idx % 28;
        int pary = (y + 1) & 1, parx = (x + 1) & 1;
        int iya = (y + 1 - pary) >> 1, iyb = iya - 1;
        int ixa = (x + 1 - parx) >> 1, ixb = ixa - 1;
        bool vya = iya < 14, vyb = iyb >= 0, vxa = ixa < 14, vxb = ixb >= 0;
        float v = bias;
        if (vya && vxa) { int off = iya * 14 + ixa, kk = pary * 4 + parx;
#pragma unroll
            for (int i = 0; i < 32; i++) v = fmaf(si[i * 196 + off], sw[i * 16 + kk], v); }
        if (vya && vxb) { int off = iya * 14 + ixb, kk = pary * 4 + parx + 2;
#pragma unroll
            for (int i = 0; i < 32; i++) v = fmaf(si[i * 196 + off], sw[i * 16 + kk], v); }
        if (vyb && vxa) { int off = iyb * 14 + ixa, kk = (pary + 2) * 4 + parx;
#pragma unroll
            for (int i = 0; i < 32; i++) v = fmaf(si[i * 196 + off], sw[i * 16 + kk], v); }
        if (vyb && vxb) { int off = iyb * 14 + ixb, kk = (pary + 2) * 4 + parx + 2;
#pragma unroll
            for (int i = 0; i < 32; i++) v = fmaf(si[i * 196 + off], sw[i * 16 + kk], v); }
        outp[b * 784 + idx] = 1.f / (1.f + expf(-v));
    }
    if (b == 0 && t == 0 && lossp) *lossp = (float)(1.2 * g_stats[ST_LOSS] / 200704.0);
}

// ---------------- host ----------------
extern "C" void kernel_launch(void* const* d_in, const int* in_sizes, int n_in,
                              void* d_out, int out_size) {
    const float* x    = (const float*)d_in[0];
    const float* ew1  = (const float*)d_in[1];
    const float* eb1  = (const float*)d_in[2];
    const float* g1   = (const float*)d_in[3];
    const float* b1   = (const float*)d_in[4];
    const float* ew2  = (const float*)d_in[5];
    const float* eb2  = (const float*)d_in[6];
    const float* g2   = (const float*)d_in[7];
    const float* b2   = (const float*)d_in[8];
    const float* embed= (const float*)d_in[9];
    const float* dw1  = (const float*)d_in[10];
    const float* dbi1 = (const float*)d_in[11];
    const float* dg1  = (const float*)d_in[12];
    const float* dbb1 = (const float*)d_in[13];
    const float* dw2  = (const float*)d_in[14];
    const float* dbi2 = (const float*)d_in[15];
    const float* dg2  = (const float*)d_in[16];
    const float* dbb2 = (const float*)d_in[17];
    const float* tw1  = (const float*)d_in[18];
    const float* tbi1 = (const float*)d_in[19];
    const float* dg3  = (const float*)d_in[20];
    const float* dbb3 = (const float*)d_in[21];
    const float* tw2  = (const float*)d_in[22];
    const float* tbi2 = (const float*)d_in[23];

    const int OUT_IMG = NB * 784;     // 1605632
    const int OUT_CLS = NB * 49;      // 100352
    float* out = (float*)d_out;
    float* cls   = (out_size >= OUT_IMG + OUT_CLS) ? out + OUT_IMG : nullptr;
    float* lossp = (out_size >= OUT_IMG + OUT_CLS + 1) ? out + OUT_IMG + OUT_CLS : nullptr;

    k0_zero<<<1, 128>>>();
    k1_conv1<<<NB, 224>>>(x, ew1, eb1);
    k2_conv2<<<NB, 128>>>(ew2, eb2, g1, b1);
    k3_vq<<<NB, 128>>>(embed, g2, b2, dw1, dbi1, cls);
    k4_dec2<<<NB, 128>>>(dg1, dbb1, dw2, dbi2);
    k5_convt1<<<NB, 224>>>(dg2, dbb2, tw1, tbi1);
    k6_convt2<<<NB, 256>>>(dg3, dbb3, tw2, tbi2, out, lossp);
}